// round 7
// baseline (speedup 1.0000x reference)
#include <cuda_runtime.h>
#include <math_constants.h>

// InstanceAwarePointMatching — fused dual top-k (K=3) scatter.
// score = exp(x); top-3 along S per (p,r) and top-3 along R per (p,s).
// out (floats): [0,PRS) = score_map, [PRS,2PRS) = corr_map (0.0/1.0).
// Masks arrive as int32 (bool promoted). exp monotonic -> topk on raw x.

static __device__ __forceinline__ void insert3(float v, int i,
                                               float& v0, int& i0,
                                               float& v1, int& i1,
                                               float& v2, int& i2) {
    // strict > keeps earlier index first on ties (matches jax top_k)
    if (v > v0)      { v2 = v1; i2 = i1; v1 = v0; i1 = i0; v0 = v; i0 = i; }
    else if (v > v1) { v2 = v1; i2 = i1; v1 = v;  i1 = i; }
    else if (v > v2) { v2 = v;  i2 = i; }
}

__global__ __launch_bounds__(256)
void pm_kernel(const float* __restrict__ x,     // [P,256,256]
               const int*   __restrict__ refm,  // [P,256] int32 bool
               const int*   __restrict__ srcm,  // [P,256] int32 bool
               float* __restrict__ out,          // [2*PRS] floats
               int PRS)
{
    const int R = 256, S = 256;
    const int p    = blockIdx.x;
    const int t    = threadIdx.x;
    const int lane = t & 31;
    const int warp = t >> 5;

    __shared__ float         tile[32][256];   // 32 KB strip of raw x
    __shared__ float         rowval[256][3];  // raw top-3 values per row
    __shared__ int           rowidx[256][3];  // their S-indices
    __shared__ unsigned char s_refm[256];
    __shared__ unsigned char s_srcm[256];

    s_refm[t] = (unsigned char)(refm[p * R + t] != 0);
    s_srcm[t] = (unsigned char)(srcm[p * S + t] != 0);

    const float* xp = x + (size_t)p * R * S;

    // per-thread (column t) top-3 along R
    float cv0 = -CUDART_INF_F, cv1 = -CUDART_INF_F, cv2 = -CUDART_INF_F;
    int   ci0 = 0, ci1 = 0, ci2 = 0;

    #pragma unroll 1
    for (int strip = 0; strip < 8; ++strip) {
        const float* xs = xp + strip * 32 * S;
        // load strip: thread t loads column t of 32 rows (fully coalesced)
        #pragma unroll
        for (int j = 0; j < 32; ++j) {
            float v = xs[j * 256 + t];
            tile[j][t] = v;
            insert3(v, strip * 32 + j, cv0, ci0, cv1, ci1, cv2, ci2);
        }
        __syncthreads();

        // row top-3: warp w handles rows [w*4, w*4+4) of this strip
        #pragma unroll
        for (int q = 0; q < 4; ++q) {
            int j = warp * 4 + q;
            int r = strip * 32 + j;
            float c[8];
            #pragma unroll
            for (int k = 0; k < 8; ++k) c[k] = tile[j][lane + 32 * k];

            #pragma unroll
            for (int round = 0; round < 3; ++round) {
                float bv = c[0]; int bslot = 0;
                #pragma unroll
                for (int k = 1; k < 8; ++k)
                    if (c[k] > bv) { bv = c[k]; bslot = k; }
                int bi = lane + 32 * bslot;     // S-index
                #pragma unroll
                for (int off = 16; off; off >>= 1) {
                    float ov = __shfl_xor_sync(0xffffffffu, bv, off);
                    int   oi = __shfl_xor_sync(0xffffffffu, bi, off);
                    if (ov > bv || (ov == bv && oi < bi)) { bv = ov; bi = oi; }
                }
                if ((bi & 31) == lane) c[bi >> 5] = -CUDART_INF_F;  // owner retires winner
                if (lane == 0) { rowval[r][round] = bv; rowidx[r][round] = bi; }
            }
        }
        __syncthreads();
    }

    // ---- phase A: zero this block's output slices (vectorized) ----
    float* score = out;
    float* corr  = out + PRS;
    size_t sbase = (size_t)p * R * S;
    float4 z = make_float4(0.f, 0.f, 0.f, 0.f);
    float4* s4 = (float4*)(score + sbase);
    float4* c4 = (float4*)(corr  + sbase);
    #pragma unroll 4
    for (int j = t; j < (R * S) / 4; j += 256) { s4[j] = z; c4[j] = z; }
    __syncthreads();   // zeros visible block-wide before scatter

    // ---- phase B: scatter top-k winners ----
    float* sp = score + sbase;
    float* cp = corr  + sbase;
    bool sm_t = s_srcm[t] != 0;

    // column (src-direction) winners: column t, rows ci0..2
    {
        int   ris[3] = {ci0, ci1, ci2};
        float vs [3] = {cv0, cv1, cv2};
        #pragma unroll
        for (int k = 0; k < 3; ++k) {
            int r = ris[k];
            float ev = __expf(vs[k]);
            atomicAdd(&sp[r * 256 + t], 0.5f * ev);
            if (ev > 0.0f && sm_t && s_refm[r]) cp[r * 256 + t] = 1.0f;
        }
    }
    // row (ref-direction) winners: 256 rows * 3 entries, spread over threads
    for (int e = t; e < 768; e += 256) {
        int r = e / 3;
        int k = e - 3 * r;
        int idx = rowidx[r][k];
        float ev = __expf(rowval[r][k]);
        atomicAdd(&sp[r * 256 + idx], 0.5f * ev);
        if (ev > 0.0f && s_refm[r] && s_srcm[idx]) cp[r * 256 + idx] = 1.0f;
    }
}

extern "C" void kernel_launch(void* const* d_in, const int* in_sizes, int n_in,
                              void* d_out, int out_size) {
    const float* x    = (const float*)d_in[0];
    // d_in[1] = node_corr_scores (unused: conditional=False)
    const int*   refm = (const int*)d_in[2];
    const int*   srcm = (const int*)d_in[3];
    int P   = in_sizes[1];       // node_corr_scores has P elements
    int PRS = in_sizes[0];       // P*R*S

    pm_kernel<<<P, 256>>>(x, refm, srcm, (float*)d_out, PRS);
}

// round 12
// speedup vs baseline: 1.0417x; 1.0417x over previous
#include <cuda_runtime.h>
#include <math_constants.h>

// InstanceAwarePointMatching — fused dual top-k (K=3) scatter, v2b.
// Issue-bound fix: guarded insert3 (rare slow path), per-thread row ownership
// (no warp-collective topk, no smem tile, 1 sync), scatter-by-owner.
// Batched loads (MLP>=8) before guarded inserts so predication can't
// serialize the memory stream.
// out (floats): [0,PRS) = score_map, [PRS,2PRS) = corr_map (0.0/1.0).
// Masks arrive as int32. exp monotonic -> topk on raw x, exp winners only.

static __device__ __forceinline__ void insert3_full(float v, int i,
                                                    float& v0, int& i0,
                                                    float& v1, int& i1,
                                                    float& v2, int& i2) {
    // caller guarantees v > v2; strict > keeps earlier index on ties
    if (v > v0)      { v2 = v1; i2 = i1; v1 = v0; i1 = i0; v0 = v; i0 = i; }
    else if (v > v1) { v2 = v1; i2 = i1; v1 = v;  i1 = i; }
    else             { v2 = v;  i2 = i; }
}

#define TRY_INS(v, i, v0, i0, v1, i1, v2, i2) \
    do { if ((v) > (v2)) insert3_full((v), (i), v0, i0, v1, i1, v2, i2); } while (0)

__global__ __launch_bounds__(256, 4)
void pm_kernel(const float* __restrict__ x,     // [P,256,256]
               const int*   __restrict__ refm,  // [P,256] int32 bool
               const int*   __restrict__ srcm,  // [P,256] int32 bool
               float* __restrict__ out,          // [2*PRS] floats
               int PRS)
{
    const int R = 256, S = 256;
    const int p = blockIdx.x;
    const int t = threadIdx.x;

    __shared__ unsigned char s_refm[256];
    __shared__ unsigned char s_srcm[256];
    s_refm[t] = (unsigned char)(refm[p * R + t] != 0);
    s_srcm[t] = (unsigned char)(srcm[p * S + t] != 0);

    const float* xp = x + ((size_t)p << 16);

    // ---- pass 1: column top-3 (thread t owns column t; coalesced) ----
    float cv0 = -CUDART_INF_F, cv1 = -CUDART_INF_F, cv2 = -CUDART_INF_F;
    int   ci0 = 0, ci1 = 0, ci2 = 0;
    {
        const float* cp0 = xp + t;
        #pragma unroll 1
        for (int j = 0; j < 256; j += 8) {
            float b[8];
            #pragma unroll
            for (int u = 0; u < 8; ++u)       // 8 independent LDGs first
                b[u] = cp0[(j + u) * 256];
            #pragma unroll
            for (int u = 0; u < 8; ++u)       // then guarded inserts
                TRY_INS(b[u], j + u, cv0, ci0, cv1, ci1, cv2, ci2);
        }
    }

    // ---- pass 2: row top-3 (thread t owns row t; float4, L1 line reuse) ----
    float rv0 = -CUDART_INF_F, rv1 = -CUDART_INF_F, rv2 = -CUDART_INF_F;
    int   ri0 = 0, ri1 = 0, ri2 = 0;
    {
        const float4* rp = (const float4*)(xp + t * 256);
        #pragma unroll 1
        for (int i = 0; i < 64; i += 2) {
            float4 a = rp[i];
            float4 b = rp[i + 1];
            TRY_INS(a.x, 4 * i,     rv0, ri0, rv1, ri1, rv2, ri2);
            TRY_INS(a.y, 4 * i + 1, rv0, ri0, rv1, ri1, rv2, ri2);
            TRY_INS(a.z, 4 * i + 2, rv0, ri0, rv1, ri1, rv2, ri2);
            TRY_INS(a.w, 4 * i + 3, rv0, ri0, rv1, ri1, rv2, ri2);
            TRY_INS(b.x, 4 * i + 4, rv0, ri0, rv1, ri1, rv2, ri2);
            TRY_INS(b.y, 4 * i + 5, rv0, ri0, rv1, ri1, rv2, ri2);
            TRY_INS(b.z, 4 * i + 6, rv0, ri0, rv1, ri1, rv2, ri2);
            TRY_INS(b.w, 4 * i + 7, rv0, ri0, rv1, ri1, rv2, ri2);
        }
    }

    // ---- zero this block's output slices (vectorized) ----
    float* score = out;
    float* corr  = out + PRS;
    size_t sbase = (size_t)p * R * S;
    float4 z = make_float4(0.f, 0.f, 0.f, 0.f);
    float4* s4 = (float4*)(score + sbase);
    float4* c4 = (float4*)(corr  + sbase);
    #pragma unroll 8
    for (int k = t; k < (R * S) / 4; k += 256) { s4[k] = z; c4[k] = z; }

    __syncthreads();   // zeros + masks visible block-wide before scatter

    // ---- scatter-by-owner ----
    float* sp = score + sbase;
    float* cp = corr  + sbase;
    const bool sm_t = s_srcm[t] != 0;   // src mask for own column
    const bool rm_t = s_refm[t] != 0;   // ref mask for own row

    // column winners: column t, rows ci0..2 (src-direction top-k)
    {
        int   ris[3] = {ci0, ci1, ci2};
        float vs [3] = {cv0, cv1, cv2};
        #pragma unroll
        for (int k = 0; k < 3; ++k) {
            int r = ris[k];
            float ev = __expf(vs[k]);
            atomicAdd(&sp[r * 256 + t], 0.5f * ev);
            if (ev > 0.0f && sm_t && s_refm[r]) cp[r * 256 + t] = 1.0f;
        }
    }
    // row winners: row t, cols ri0..2 (ref-direction top-k)
    {
        int   cis[3] = {ri0, ri1, ri2};
        float vs [3] = {rv0, rv1, rv2};
        #pragma unroll
        for (int k = 0; k < 3; ++k) {
            int c = cis[k];
            float ev = __expf(vs[k]);
            atomicAdd(&sp[t * 256 + c], 0.5f * ev);
            if (ev > 0.0f && rm_t && s_srcm[c]) cp[t * 256 + c] = 1.0f;
        }
    }
}

extern "C" void kernel_launch(void* const* d_in, const int* in_sizes, int n_in,
                              void* d_out, int out_size) {
    const float* x    = (const float*)d_in[0];
    // d_in[1] = node_corr_scores (unused: conditional=False)
    const int*   refm = (const int*)d_in[2];
    const int*   srcm = (const int*)d_in[3];
    int P   = in_sizes[1];       // node_corr_scores has P elements
    int PRS = in_sizes[0];       // P*R*S

    pm_kernel<<<P, 256>>>(x, refm, srcm, (float*)d_out, PRS);
}

// round 13
// speedup vs baseline: 1.2394x; 1.1898x over previous
#include <cuda_runtime.h>
#include <math_constants.h>

// InstanceAwarePointMatching — fused dual top-k (K=3) scatter, v3.
// 512-thread blocks: threads [0,256) do the column top-k (coalesced),
// threads [256,512) CONCURRENTLY do the row top-k (float4) on the same
// 256KB tile -> second ordering hits L2, DRAM read ~halves, and 2x TLP
// hides latency. Guarded insert3 keeps the hot path at 1 cmp/element.
// out (floats): [0,PRS) = score_map, [PRS,2PRS) = corr_map (0.0/1.0).
// Masks arrive as int32. exp monotonic -> topk on raw x, exp winners only.

static __device__ __forceinline__ void insert3_full(float v, int i,
                                                    float& v0, int& i0,
                                                    float& v1, int& i1,
                                                    float& v2, int& i2) {
    // caller guarantees v > v2; strict > keeps earlier index on ties
    if (v > v0)      { v2 = v1; i2 = i1; v1 = v0; i1 = i0; v0 = v; i0 = i; }
    else if (v > v1) { v2 = v1; i2 = i1; v1 = v;  i1 = i; }
    else             { v2 = v;  i2 = i; }
}

#define TRY_INS(v, i, v0, i0, v1, i1, v2, i2) \
    do { if ((v) > (v2)) insert3_full((v), (i), v0, i0, v1, i1, v2, i2); } while (0)

__global__ __launch_bounds__(512, 4)
void pm_kernel(const float* __restrict__ x,     // [P,256,256]
               const int*   __restrict__ refm,  // [P,256] int32 bool
               const int*   __restrict__ srcm,  // [P,256] int32 bool
               float* __restrict__ out,          // [2*PRS] floats
               int PRS)
{
    const int R = 256, S = 256;
    const int p  = blockIdx.x;
    const int t  = threadIdx.x;       // 0..511
    const int tt = t & 255;           // lane within half

    __shared__ unsigned char s_refm[256];
    __shared__ unsigned char s_srcm[256];
    if (t < 256) {
        s_refm[t] = (unsigned char)(refm[p * R + t] != 0);
        s_srcm[t] = (unsigned char)(srcm[p * S + t] != 0);
    }

    const float* xp = x + ((size_t)p << 16);

    // per-thread top-3 state (column top-3 for half A, row top-3 for half B)
    float v0 = -CUDART_INF_F, v1 = -CUDART_INF_F, v2 = -CUDART_INF_F;
    int   i0 = 0, i1 = 0, i2 = 0;

    if (t < 256) {
        // ---- half A: column top-3 (thread tt owns column tt; coalesced) ----
        const float* cp0 = xp + tt;
        #pragma unroll 1
        for (int j = 0; j < 256; j += 8) {
            float b[8];
            #pragma unroll
            for (int u = 0; u < 8; ++u)       // 8 independent LDGs first
                b[u] = cp0[(j + u) * 256];
            #pragma unroll
            for (int u = 0; u < 8; ++u)       // then guarded inserts
                TRY_INS(b[u], j + u, v0, i0, v1, i1, v2, i2);
        }
    } else {
        // ---- half B: row top-3 (thread tt owns row tt; float4, L2 reuse) ----
        const float4* rp = (const float4*)(xp + tt * 256);
        #pragma unroll 1
        for (int i = 0; i < 64; i += 4) {
            float4 a = rp[i];
            float4 b = rp[i + 1];
            float4 c = rp[i + 2];
            float4 d = rp[i + 3];
            TRY_INS(a.x, 4*i,      v0, i0, v1, i1, v2, i2);
            TRY_INS(a.y, 4*i + 1,  v0, i0, v1, i1, v2, i2);
            TRY_INS(a.z, 4*i + 2,  v0, i0, v1, i1, v2, i2);
            TRY_INS(a.w, 4*i + 3,  v0, i0, v1, i1, v2, i2);
            TRY_INS(b.x, 4*i + 4,  v0, i0, v1, i1, v2, i2);
            TRY_INS(b.y, 4*i + 5,  v0, i0, v1, i1, v2, i2);
            TRY_INS(b.z, 4*i + 6,  v0, i0, v1, i1, v2, i2);
            TRY_INS(b.w, 4*i + 7,  v0, i0, v1, i1, v2, i2);
            TRY_INS(c.x, 4*i + 8,  v0, i0, v1, i1, v2, i2);
            TRY_INS(c.y, 4*i + 9,  v0, i0, v1, i1, v2, i2);
            TRY_INS(c.z, 4*i + 10, v0, i0, v1, i1, v2, i2);
            TRY_INS(c.w, 4*i + 11, v0, i0, v1, i1, v2, i2);
            TRY_INS(d.x, 4*i + 12, v0, i0, v1, i1, v2, i2);
            TRY_INS(d.y, 4*i + 13, v0, i0, v1, i1, v2, i2);
            TRY_INS(d.z, 4*i + 14, v0, i0, v1, i1, v2, i2);
            TRY_INS(d.w, 4*i + 15, v0, i0, v1, i1, v2, i2);
        }
    }

    // ---- zero this block's output slices (all 512 threads) ----
    float* score = out;
    float* corr  = out + PRS;
    size_t sbase = (size_t)p * R * S;
    float4 z = make_float4(0.f, 0.f, 0.f, 0.f);
    float4* s4 = (float4*)(score + sbase);
    float4* c4 = (float4*)(corr  + sbase);
    #pragma unroll 8
    for (int k = t; k < (R * S) / 4; k += 512) { s4[k] = z; c4[k] = z; }

    __syncthreads();   // zeros + masks visible block-wide before scatter

    // ---- scatter-by-owner ----
    float* sp = score + sbase;
    float* cp = corr  + sbase;

    if (t < 256) {
        // column winners: column tt, rows i0..2 (src-direction top-k)
        const bool sm = s_srcm[tt] != 0;
        int   ris[3] = {i0, i1, i2};
        float vs [3] = {v0, v1, v2};
        #pragma unroll
        for (int k = 0; k < 3; ++k) {
            int r = ris[k];
            float ev = __expf(vs[k]);
            atomicAdd(&sp[r * 256 + tt], 0.5f * ev);
            if (ev > 0.0f && sm && s_refm[r]) cp[r * 256 + tt] = 1.0f;
        }
    } else {
        // row winners: row tt, cols i0..2 (ref-direction top-k)
        const bool rm = s_refm[tt] != 0;
        int   cis[3] = {i0, i1, i2};
        float vs [3] = {v0, v1, v2};
        #pragma unroll
        for (int k = 0; k < 3; ++k) {
            int c = cis[k];
            float ev = __expf(vs[k]);
            atomicAdd(&sp[tt * 256 + c], 0.5f * ev);
            if (ev > 0.0f && rm && s_srcm[c]) cp[tt * 256 + c] = 1.0f;
        }
    }
}

extern "C" void kernel_launch(void* const* d_in, const int* in_sizes, int n_in,
                              void* d_out, int out_size) {
    const float* x    = (const float*)d_in[0];
    // d_in[1] = node_corr_scores (unused: conditional=False)
    const int*   refm = (const int*)d_in[2];
    const int*   srcm = (const int*)d_in[3];
    int P   = in_sizes[1];       // node_corr_scores has P elements
    int PRS = in_sizes[0];       // P*R*S

    pm_kernel<<<P, 512>>>(x, refm, srcm, (float*)d_out, PRS);
}